// round 5
// baseline (speedup 1.0000x reference)
#include <cuda_runtime.h>
#include <cuda_bf16.h>
#include <cstdint>

#define WARPS_PER_CTA 4
#define ROWS_PER_WARP 8
// per-warp scratch (floats), total 1792 = 7KB:
// [0,1024)     phase: points for 4 rows (XY pairs at P*256, Z at 512+P*128)
//              later: act[128] rows0-3 at ch*4, rows4-7 at 512+ch*4, h2[32][8] at ch*8
// [1024,1792)  v[96][8] at 1024+ch*8+r ; later h1[64][8] at 1024+ch*8 ; h3[16][8] at 1536+ch*8
#define BUF_FLOATS 1792

typedef unsigned long long u64;

__device__ __forceinline__ u64 fma2(u64 a, u64 b, u64 c) {
    u64 d;
    asm("fma.rn.f32x2 %0, %1, %2, %3;" : "=l"(d) : "l"(a), "l"(b), "l"(c));
    return d;
}
__device__ __forceinline__ u64 mul2(u64 a, u64 b) {
    u64 d;
    asm("mul.rn.f32x2 %0, %1, %2;" : "=l"(d) : "l"(a), "l"(b));
    return d;
}
__device__ __forceinline__ u64 pack2(float x, float y) {
    u64 d;
    asm("mov.b64 %0, {%1, %2};" : "=l"(d) : "r"(__float_as_uint(x)), "r"(__float_as_uint(y)));
    return d;
}
__device__ __forceinline__ u64 splat2(float x) {
    u64 d;
    asm("mov.b64 %0, {%1, %1};" : "=l"(d) : "r"(__float_as_uint(x)));
    return d;
}
__device__ __forceinline__ void unpack2(u64 a, float& x, float& y) {
    unsigned lo, hi;
    asm("mov.b64 {%0, %1}, %2;" : "=r"(lo), "=r"(hi) : "l"(a));
    x = __uint_as_float(lo); y = __uint_as_float(hi);
}
// No max.f32x2 in PTX — do two scalar FMNMX on the register halves.
// The mov.b64 pack/unpack is register-pair bookkeeping that ptxas folds away.
__device__ __forceinline__ u64 max2(u64 a, u64 b) {
    float a0, a1, b0, b1;
    unpack2(a, a0, a1); unpack2(b, b0, b1);
    return pack2(fmaxf(a0, b0), fmaxf(a1, b1));
}
__device__ __forceinline__ u64 relu2(u64 x) {
    float x0, x1;
    unpack2(x, x0, x1);
    return pack2(fmaxf(x0, 0.f), fmaxf(x1, 0.f));
}
__device__ __forceinline__ u64 leaky2(u64 x) {
    float x0, x1;
    unpack2(x, x0, x1);
    return pack2(fmaxf(x0, 0.2f * x0), fmaxf(x1, 0.2f * x1));
}

__global__ __launch_bounds__(WARPS_PER_CTA * 32)
void flatnet_r8p_kernel(
    const float* __restrict__ pgi,
    const float* __restrict__ W_lift, const float* __restrict__ b_lift,
    const float* __restrict__ W_code, const float* __restrict__ b_code,
    const float* __restrict__ W_h1,   const float* __restrict__ b_h1,
    const float* __restrict__ W_h2,   const float* __restrict__ b_h2,
    const float* __restrict__ W_h3,   const float* __restrict__ b_h3,
    const float* __restrict__ W_h4,   const float* __restrict__ b_h4,
    float* __restrict__ out)
{
    __shared__ __align__(16) float sbuf[WARPS_PER_CTA][BUF_FLOATS];

    const int warp = threadIdx.x >> 5;
    const int lane = threadIdx.x & 31;
    const int wrow = (blockIdx.x * WARPS_PER_CTA + warp) * ROWS_PER_WARP; // base row = b*1024+g
    float* buf = sbuf[warp];

    const int ld3 = lane / 3, lm3 = lane - ld3 * 3;

    // lift weights (lane = channel)
    const u64 ww0 = splat2(__ldg(W_lift + lane));
    const u64 ww1 = splat2(__ldg(W_lift + 32 + lane));
    const u64 ww2 = splat2(__ldg(W_lift + 64 + lane));
    const u64 bb  = splat2(__ldg(b_lift + lane));

    const int b = wrow >> 10, g = wrow & 1023;
    const int gi = g >> 5, gj = g & 31;  // gj..gj+7 never wraps (wrow multiple of 8)
    const float* base = pgi + ((size_t)b * 65536 + (size_t)(gi * 8) * 256 + (size_t)(gj * 8)) * 3;

    // ---- Two phases: stage+lift rows 0-3, then rows 4-7 (same points buffer) ----
    #pragma unroll 1
    for (int ph = 0; ph < 2; ph++) {
        if (lane < 24) {
            #pragma unroll
            for (int q = 0; q < 4; q++) {
                const int P = q >> 1, s = q & 1;
                const float* bq = base + (ph * 4 + q) * 24;
                #pragma unroll
                for (int gr = 0; gr < 8; gr++) {
                    const float val = bq[(size_t)gr * 768 + lane];
                    const int p = gr * 8 + ld3;
                    int off;
                    if (lm3 == 2) off = 512 + P * 128 + p * 2 + s;      // z
                    else          off = P * 256 + p * 4 + lm3 * 2 + s;  // x / y
                    buf[off] = val;
                }
            }
        }
        __syncwarp();

        #pragma unroll
        for (int P = 0; P < 2; P++) {
            const float* XY = buf + P * 256;
            const float* Z  = buf + 512 + P * 128;
            u64 mi = pack2(-3.0e38f, -3.0e38f);
            u64 mt = mi, mo = mi;
            #pragma unroll
            for (int p = 0; p < 64; p += 2) {
                const ulonglong2 xyA = *(const ulonglong2*)(XY + p * 4);
                const ulonglong2 xyB = *(const ulonglong2*)(XY + p * 4 + 4);
                const ulonglong2 zz  = *(const ulonglong2*)(Z + p * 2);
                const u64 hA = fma2(xyA.x, ww0, fma2(xyA.y, ww1, fma2(zz.x, ww2, bb)));
                const u64 hB = fma2(xyB.x, ww0, fma2(xyB.y, ww1, fma2(zz.y, ww2, bb)));
                {
                    const int r = p >> 3, c = p & 7;
                    const int d = min(min(r, c), min(7 - r, 7 - c));
                    if (d == 3)      mi = max2(mi, hA);
                    else if (d == 2) mt = max2(mt, hA);
                    else             mo = max2(mo, hA);
                }
                {
                    const int r = (p + 1) >> 3, c = (p + 1) & 7;
                    const int d = min(min(r, c), min(7 - r, 7 - c));
                    if (d == 3)      mi = max2(mi, hB);
                    else if (d == 2) mt = max2(mt, hB);
                    else             mo = max2(mo, hB);
                }
            }
            const int qb = ph * 4 + P * 2;  // row-pair slot 0..6 step 2
            *(u64*)(buf + 1024 + lane * 8 + qb)        = leaky2(mi);
            *(u64*)(buf + 1024 + (32 + lane) * 8 + qb) = leaky2(mt);
            *(u64*)(buf + 1024 + (64 + lane) * 8 + qb) = leaky2(mo);
        }
        __syncwarp();
    }

    // ---- v_code[128] = leaky(v @ W_code + b); lane owns j=lane+32o; 8 rows packed ----
    {
        u64 acc[4][4];
        #pragma unroll
        for (int o = 0; o < 4; o++) {
            const u64 bsp = splat2(__ldg(b_code + 32 * o + lane));
            acc[o][0] = bsp; acc[o][1] = bsp; acc[o][2] = bsp; acc[o][3] = bsp;
        }
        #pragma unroll 4
        for (int i = 0; i < 96; i++) {
            const ulonglong2 vab = *(const ulonglong2*)(buf + 1024 + i * 8);
            const ulonglong2 vcd = *(const ulonglong2*)(buf + 1024 + i * 8 + 4);
            const float* wr = W_code + i * 128 + lane;
            #pragma unroll
            for (int o = 0; o < 4; o++) {
                const u64 ww = splat2(__ldg(wr + 32 * o));
                acc[o][0] = fma2(vab.x, ww, acc[o][0]);
                acc[o][1] = fma2(vab.y, ww, acc[o][1]);
                acc[o][2] = fma2(vcd.x, ww, acc[o][2]);
                acc[o][3] = fma2(vcd.y, ww, acc[o][3]);
            }
        }
        __syncwarp();
        #pragma unroll
        for (int o = 0; o < 4; o++) {
            const int ch = 32 * o + lane;
            ulonglong2 rA = { leaky2(acc[o][0]), leaky2(acc[o][1]) };
            ulonglong2 rB = { leaky2(acc[o][2]), leaky2(acc[o][3]) };
            *(ulonglong2*)(buf + ch * 4)       = rA;   // act rows 0-3
            *(ulonglong2*)(buf + 512 + ch * 4) = rB;   // act rows 4-7
        }
    }
    __syncwarp();

    // ---- h1[64] = relu(v_code @ W_h1 + b) ----
    {
        u64 acc[2][4];
        #pragma unroll
        for (int o = 0; o < 2; o++) {
            const u64 bsp = splat2(__ldg(b_h1 + 32 * o + lane));
            acc[o][0] = bsp; acc[o][1] = bsp; acc[o][2] = bsp; acc[o][3] = bsp;
        }
        #pragma unroll 4
        for (int i = 0; i < 128; i++) {
            const ulonglong2 vab = *(const ulonglong2*)(buf + i * 4);
            const ulonglong2 vcd = *(const ulonglong2*)(buf + 512 + i * 4);
            const float* wr = W_h1 + i * 64 + lane;
            #pragma unroll
            for (int o = 0; o < 2; o++) {
                const u64 ww = splat2(__ldg(wr + 32 * o));
                acc[o][0] = fma2(vab.x, ww, acc[o][0]);
                acc[o][1] = fma2(vab.y, ww, acc[o][1]);
                acc[o][2] = fma2(vcd.x, ww, acc[o][2]);
                acc[o][3] = fma2(vcd.y, ww, acc[o][3]);
            }
        }
        __syncwarp();
        #pragma unroll
        for (int o = 0; o < 2; o++) {
            const int ch = 32 * o + lane;
            ulonglong2 rA = { relu2(acc[o][0]), relu2(acc[o][1]) };
            ulonglong2 rB = { relu2(acc[o][2]), relu2(acc[o][3]) };
            *(ulonglong2*)(buf + 1024 + ch * 8)     = rA;  // h1 rows 0-3
            *(ulonglong2*)(buf + 1024 + ch * 8 + 4) = rB;  // h1 rows 4-7
        }
    }
    __syncwarp();

    // ---- h2[32] = relu(h1 @ W_h2 + b) ----
    {
        u64 acc[4];
        {
            const u64 bsp = splat2(__ldg(b_h2 + lane));
            acc[0] = bsp; acc[1] = bsp; acc[2] = bsp; acc[3] = bsp;
        }
        #pragma unroll 8
        for (int i = 0; i < 64; i++) {
            const ulonglong2 vab = *(const ulonglong2*)(buf + 1024 + i * 8);
            const ulonglong2 vcd = *(const ulonglong2*)(buf + 1024 + i * 8 + 4);
            const u64 ww = splat2(__ldg(W_h2 + i * 32 + lane));
            acc[0] = fma2(vab.x, ww, acc[0]);
            acc[1] = fma2(vab.y, ww, acc[1]);
            acc[2] = fma2(vcd.x, ww, acc[2]);
            acc[3] = fma2(vcd.y, ww, acc[3]);
        }
        __syncwarp();
        ulonglong2 rA = { relu2(acc[0]), relu2(acc[1]) };
        ulonglong2 rB = { relu2(acc[2]), relu2(acc[3]) };
        *(ulonglong2*)(buf + lane * 8)     = rA;           // h2 rows 0-3
        *(ulonglong2*)(buf + lane * 8 + 4) = rB;           // h2 rows 4-7
    }
    __syncwarp();

    // ---- h3[16] = relu(h2 @ W_h3 + b); half-warp per 4-row group ----
    {
        const int j  = lane & 15;
        const int hh = lane >> 4;
        u64 e0, e1;
        {
            const u64 bsp = splat2(__ldg(b_h3 + j));
            e0 = bsp; e1 = bsp;
        }
        #pragma unroll 8
        for (int i = 0; i < 32; i++) {
            const ulonglong2 v = *(const ulonglong2*)(buf + i * 8 + hh * 4);
            const u64 ww = splat2(__ldg(W_h3 + i * 16 + j));
            e0 = fma2(v.x, ww, e0);
            e1 = fma2(v.y, ww, e1);
        }
        ulonglong2 r = { relu2(e0), relu2(e1) };
        *(ulonglong2*)(buf + 1536 + j * 8 + hh * 4) = r;   // h3[16][8]
    }
    __syncwarp();

    // ---- out[3] per row; lanes 0..23: row q=ld3, comp lm3 -> 24 contiguous floats ----
    if (lane < 24) {
        float o = __ldg(b_h4 + lm3);
        #pragma unroll
        for (int i = 0; i < 16; i++)
            o = fmaf(buf[1536 + i * 8 + ld3], __ldg(W_h4 + i * 3 + lm3), o);
        out[(size_t)wrow * 3 + lane] = o;
    }
}

extern "C" void kernel_launch(void* const* d_in, const int* in_sizes, int n_in,
                              void* d_out, int out_size)
{
    const float* pgi    = (const float*)d_in[0];
    const float* W_lift = (const float*)d_in[1];
    const float* b_lift = (const float*)d_in[2];
    const float* W_code = (const float*)d_in[3];
    const float* b_code = (const float*)d_in[4];
    const float* W_h1   = (const float*)d_in[5];
    const float* b_h1   = (const float*)d_in[6];
    const float* W_h2   = (const float*)d_in[7];
    const float* b_h2   = (const float*)d_in[8];
    const float* W_h3   = (const float*)d_in[9];
    const float* b_h3   = (const float*)d_in[10];
    const float* W_h4   = (const float*)d_in[11];
    const float* b_h4   = (const float*)d_in[12];
    float* out = (float*)d_out;

    // 32768 rows, 8 rows/warp, 4 warps/CTA -> 1024 CTAs x 128 threads
    flatnet_r8p_kernel<<<1024, WARPS_PER_CTA * 32>>>(
        pgi, W_lift, b_lift, W_code, b_code,
        W_h1, b_h1, W_h2, b_h2, W_h3, b_h3, W_h4, b_h4, out);
}

// round 6
// speedup vs baseline: 1.0389x; 1.0389x over previous
#include <cuda_runtime.h>
#include <cuda_bf16.h>
#include <cstdint>

#define WARPS_PER_CTA 2
#define ROWS_PER_WARP 8
// per-warp scratch layout (floats):
// [0,1024)    ptsXY: pair P(0..3), point p(0..63): [x0,x1,y0,y1]   (later act[128] A/B halves)
// [1024,1536) ptsZ : pair P, point p: [z0,z1]
// [1536,1920) vA: ring-major i'=ch*3+ring (0..95) x rows0..3  (later h1A[64]x4, h3A[16]x4)
// [1920,2304) vB: same, rows4..7                              (later h1B, h3B)
#define BUF_FLOATS 2304

typedef unsigned long long u64;

__device__ __forceinline__ u64 fma2(u64 a, u64 b, u64 c) {
    u64 d;
    asm("fma.rn.f32x2 %0, %1, %2, %3;" : "=l"(d) : "l"(a), "l"(b), "l"(c));
    return d;
}
__device__ __forceinline__ u64 pack2(float x, float y) {
    u64 d;
    asm("mov.b64 %0, {%1, %2};" : "=l"(d) : "r"(__float_as_uint(x)), "r"(__float_as_uint(y)));
    return d;
}
__device__ __forceinline__ u64 splat2(float x) {
    u64 d;
    asm("mov.b64 %0, {%1, %1};" : "=l"(d) : "r"(__float_as_uint(x)));
    return d;
}
__device__ __forceinline__ void unpack2(u64 a, float& x, float& y) {
    unsigned lo, hi;
    asm("mov.b64 {%0, %1}, %2;" : "=r"(lo), "=r"(hi) : "l"(a));
    x = __uint_as_float(lo); y = __uint_as_float(hi);
}
// No max.f32x2 in PTX: two scalar FMNMX on the halves; movs fold into reg-pair alloc.
__device__ __forceinline__ u64 max2(u64 a, u64 b) {
    float a0, a1, b0, b1;
    unpack2(a, a0, a1); unpack2(b, b0, b1);
    return pack2(fmaxf(a0, b0), fmaxf(a1, b1));
}
__device__ __forceinline__ u64 relu2(u64 x) {
    float x0, x1;
    unpack2(x, x0, x1);
    return pack2(fmaxf(x0, 0.f), fmaxf(x1, 0.f));
}
__device__ __forceinline__ u64 leaky2(u64 x) {
    float x0, x1;
    unpack2(x, x0, x1);
    return pack2(fmaxf(x0, 0.2f * x0), fmaxf(x1, 0.2f * x1));
}

__global__ __launch_bounds__(WARPS_PER_CTA * 32, 12)
void flatnet_r6_kernel(
    const float* __restrict__ pgi,
    const float* __restrict__ W_lift, const float* __restrict__ b_lift,
    const float* __restrict__ W_code, const float* __restrict__ b_code,
    const float* __restrict__ W_h1,   const float* __restrict__ b_h1,
    const float* __restrict__ W_h2,   const float* __restrict__ b_h2,
    const float* __restrict__ W_h3,   const float* __restrict__ b_h3,
    const float* __restrict__ W_h4,   const float* __restrict__ b_h4,
    float* __restrict__ out)
{
    __shared__ __align__(16) float sbuf[WARPS_PER_CTA][BUF_FLOATS];

    const int warp = threadIdx.x >> 5;
    const int lane = threadIdx.x & 31;
    const int wrow = (blockIdx.x * WARPS_PER_CTA + warp) * ROWS_PER_WARP; // base row = b*1024+g
    float* buf = sbuf[warp];

    const int ld3 = lane / 3, lm3 = lane - ld3 * 3;

    // ---- Stage 8 rows' 8x8 point blocks into packed-pair layout (one shot) ----
    {
        const int b = wrow >> 10, g = wrow & 1023;
        const int gi = g >> 5, gj = g & 31;          // gj..gj+7 never wraps (wrow mult of 8)
        const float* base = pgi + ((size_t)b * 65536 + (size_t)(gi * 8) * 256 + (size_t)(gj * 8)) * 3;
        if (lane < 24) {
            #pragma unroll
            for (int q = 0; q < ROWS_PER_WARP; q++) {
                const int P = q >> 1, s = q & 1;
                const float* bq = base + q * 24;
                #pragma unroll
                for (int gr = 0; gr < 8; gr++) {
                    const float val = bq[(size_t)gr * 768 + lane];
                    const int p = gr * 8 + ld3;
                    int off;
                    if (lm3 == 2) off = 1024 + P * 128 + p * 2 + s;       // z
                    else          off = P * 256 + p * 4 + lm3 * 2 + s;    // x / y
                    buf[off] = val;
                }
            }
        }
    }
    __syncwarp();

    // ---- Lift (lane = channel), row-pairs packed in f32x2; ring-major v stores ----
    {
        const u64 ww0 = splat2(__ldg(W_lift + lane));
        const u64 ww1 = splat2(__ldg(W_lift + 32 + lane));
        const u64 ww2 = splat2(__ldg(W_lift + 64 + lane));
        const u64 bb  = splat2(__ldg(b_lift + lane));

        #pragma unroll
        for (int P = 0; P < 4; P++) {
            const float* XY = buf + P * 256;
            const float* Z  = buf + 1024 + P * 128;
            u64 mi = pack2(-3.0e38f, -3.0e38f);
            u64 mt = mi, mo = mi;
            #pragma unroll
            for (int p = 0; p < 64; p += 2) {
                const ulonglong2 xyA = *(const ulonglong2*)(XY + p * 4);
                const ulonglong2 xyB = *(const ulonglong2*)(XY + p * 4 + 4);
                const ulonglong2 zz  = *(const ulonglong2*)(Z + p * 2);
                const u64 hA = fma2(xyA.x, ww0, fma2(xyA.y, ww1, fma2(zz.x, ww2, bb)));
                const u64 hB = fma2(xyB.x, ww0, fma2(xyB.y, ww1, fma2(zz.y, ww2, bb)));
                {
                    const int r = p >> 3, c = p & 7;
                    const int d = min(min(r, c), min(7 - r, 7 - c));
                    if (d == 3)      mi = max2(mi, hA);
                    else if (d == 2) mt = max2(mt, hA);
                    else             mo = max2(mo, hA);
                }
                {
                    const int r = (p + 1) >> 3, c = (p + 1) & 7;
                    const int d = min(min(r, c), min(7 - r, 7 - c));
                    if (d == 3)      mi = max2(mi, hB);
                    else if (d == 2) mt = max2(mt, hB);
                    else             mo = max2(mo, hB);
                }
            }
            // v' index: i' = lane*3 + ring  (ring 0=inner,1=inter,2=outer)
            // slots: rows0-3 buffer at 1536 (pairs P=0,1), rows4-7 at 1920 (P=2,3)
            float* vdst = buf + ((P < 2) ? 1536 : 1920);
            const int qb = (P & 1) * 2;
            *(u64*)(vdst + (lane * 3 + 0) * 4 + qb) = leaky2(mi);
            *(u64*)(vdst + (lane * 3 + 1) * 4 + qb) = leaky2(mt);
            *(u64*)(vdst + (lane * 3 + 2) * 4 + qb) = leaky2(mo);
        }
    }
    __syncwarp();

    // ---- v_code[128] = leaky(v @ W_code + b); lane owns j=lane+32o; 8 rows packed.
    //      v is ring-major: i' = ch*3 + ring  <->  W_code row = ring*32 + ch. ----
    {
        u64 aA[4][2], aB[4][2];
        #pragma unroll
        for (int o = 0; o < 4; o++) {
            const u64 bsp = splat2(__ldg(b_code + 32 * o + lane));
            aA[o][0] = bsp; aA[o][1] = bsp;
            aB[o][0] = bsp; aB[o][1] = bsp;
        }
        #pragma unroll 2
        for (int ch = 0; ch < 32; ch++) {
            #pragma unroll
            for (int ring = 0; ring < 3; ring++) {
                const int ii = ch * 3 + ring;
                const ulonglong2 vA = *(const ulonglong2*)(buf + 1536 + ii * 4);
                const ulonglong2 vB = *(const ulonglong2*)(buf + 1920 + ii * 4);
                const float* wr = W_code + (ring * 32 + ch) * 128 + lane;
                #pragma unroll
                for (int o = 0; o < 4; o++) {
                    const u64 ww = splat2(__ldg(wr + 32 * o));
                    aA[o][0] = fma2(vA.x, ww, aA[o][0]);
                    aA[o][1] = fma2(vA.y, ww, aA[o][1]);
                    aB[o][0] = fma2(vB.x, ww, aB[o][0]);
                    aB[o][1] = fma2(vB.y, ww, aB[o][1]);
                }
            }
        }
        __syncwarp();
        #pragma unroll
        for (int o = 0; o < 4; o++) {
            const int ch = 32 * o + lane;
            ulonglong2 rA = { leaky2(aA[o][0]), leaky2(aA[o][1]) };
            ulonglong2 rB = { leaky2(aB[o][0]), leaky2(aB[o][1]) };
            *(ulonglong2*)(buf + ch * 4)       = rA;   // act rows 0-3
            *(ulonglong2*)(buf + 512 + ch * 4) = rB;   // act rows 4-7
        }
    }
    __syncwarp();

    // ---- h1[64] = relu(v_code @ W_h1 + b) ----
    {
        u64 cA[2][2], cB[2][2];
        #pragma unroll
        for (int o = 0; o < 2; o++) {
            const u64 bsp = splat2(__ldg(b_h1 + 32 * o + lane));
            cA[o][0] = bsp; cA[o][1] = bsp;
            cB[o][0] = bsp; cB[o][1] = bsp;
        }
        #pragma unroll 4
        for (int i = 0; i < 128; i++) {
            const ulonglong2 vA = *(const ulonglong2*)(buf + i * 4);
            const ulonglong2 vB = *(const ulonglong2*)(buf + 512 + i * 4);
            const float* wr = W_h1 + i * 64 + lane;
            #pragma unroll
            for (int o = 0; o < 2; o++) {
                const u64 ww = splat2(__ldg(wr + 32 * o));
                cA[o][0] = fma2(vA.x, ww, cA[o][0]);
                cA[o][1] = fma2(vA.y, ww, cA[o][1]);
                cB[o][0] = fma2(vB.x, ww, cB[o][0]);
                cB[o][1] = fma2(vB.y, ww, cB[o][1]);
            }
        }
        __syncwarp();
        #pragma unroll
        for (int o = 0; o < 2; o++) {
            const int ch = 32 * o + lane;
            ulonglong2 rA = { relu2(cA[o][0]), relu2(cA[o][1]) };
            ulonglong2 rB = { relu2(cB[o][0]), relu2(cB[o][1]) };
            *(ulonglong2*)(buf + 1536 + ch * 4) = rA;  // h1A
            *(ulonglong2*)(buf + 1792 + ch * 4) = rB;  // h1B
        }
    }
    __syncwarp();

    // ---- h2[32] = relu(h1 @ W_h2 + b) ----
    {
        u64 dA[2], dB[2];
        {
            const u64 bsp = splat2(__ldg(b_h2 + lane));
            dA[0] = bsp; dA[1] = bsp;
            dB[0] = bsp; dB[1] = bsp;
        }
        #pragma unroll 8
        for (int i = 0; i < 64; i++) {
            const ulonglong2 vA = *(const ulonglong2*)(buf + 1536 + i * 4);
            const ulonglong2 vB = *(const ulonglong2*)(buf + 1792 + i * 4);
            const u64 ww = splat2(__ldg(W_h2 + i * 32 + lane));
            dA[0] = fma2(vA.x, ww, dA[0]);
            dA[1] = fma2(vA.y, ww, dA[1]);
            dB[0] = fma2(vB.x, ww, dB[0]);
            dB[1] = fma2(vB.y, ww, dB[1]);
        }
        __syncwarp();
        ulonglong2 rA = { relu2(dA[0]), relu2(dA[1]) };
        ulonglong2 rB = { relu2(dB[0]), relu2(dB[1]) };
        *(ulonglong2*)(buf + lane * 4)       = rA;     // h2A
        *(ulonglong2*)(buf + 128 + lane * 4) = rB;     // h2B
    }
    __syncwarp();

    // ---- h3[16] = relu(h2 @ W_h3 + b); half-warp handles rows0-3 / rows4-7 ----
    {
        const int j  = lane & 15;
        const int hh = lane >> 4;
        u64 e0, e1;
        {
            const u64 bsp = splat2(__ldg(b_h3 + j));
            e0 = bsp; e1 = bsp;
        }
        const float* h2p = buf + hh * 128;
        #pragma unroll 8
        for (int i = 0; i < 32; i++) {
            const ulonglong2 v = *(const ulonglong2*)(h2p + i * 4);
            const u64 ww = splat2(__ldg(W_h3 + i * 16 + j));
            e0 = fma2(v.x, ww, e0);
            e1 = fma2(v.y, ww, e1);
        }
        ulonglong2 r = { relu2(e0), relu2(e1) };
        *(ulonglong2*)(buf + (hh ? 1600 : 1536) + j * 4) = r;  // h3A / h3B
    }
    __syncwarp();

    // ---- out[3] per row; lanes 0..23: q=ld3, comp=lm3 -> 24 contiguous floats ----
    if (lane < 24) {
        const float* h3p = buf + ((ld3 < 4) ? (1536 + ld3) : (1600 + (ld3 - 4)));
        float o = __ldg(b_h4 + lm3);
        #pragma unroll
        for (int i = 0; i < 16; i++)
            o = fmaf(h3p[i * 4], __ldg(W_h4 + i * 3 + lm3), o);
        out[(size_t)wrow * 3 + lane] = o;
    }
}

extern "C" void kernel_launch(void* const* d_in, const int* in_sizes, int n_in,
                              void* d_out, int out_size)
{
    const float* pgi    = (const float*)d_in[0];
    const float* W_lift = (const float*)d_in[1];
    const float* b_lift = (const float*)d_in[2];
    const float* W_code = (const float*)d_in[3];
    const float* b_code = (const float*)d_in[4];
    const float* W_h1   = (const float*)d_in[5];
    const float* b_h1   = (const float*)d_in[6];
    const float* W_h2   = (const float*)d_in[7];
    const float* b_h2   = (const float*)d_in[8];
    const float* W_h3   = (const float*)d_in[9];
    const float* b_h3   = (const float*)d_in[10];
    const float* W_h4   = (const float*)d_in[11];
    const float* b_h4   = (const float*)d_in[12];
    float* out = (float*)d_out;

    // 32768 rows, 8 rows/warp, 2 warps/CTA -> 2048 CTAs x 64 threads
    flatnet_r6_kernel<<<2048, WARPS_PER_CTA * 32>>>(
        pgi, W_lift, b_lift, W_code, b_code,
        W_h1, b_h1, W_h2, b_h2, W_h3, b_h3, W_h4, b_h4, out);
}